// round 14
// baseline (speedup 1.0000x reference)
#include <cuda_runtime.h>
#include <cstdint>

#define NN 50000
#define EE 400000
#define BBATCH 8
#define NDIM 32
#define EDIM 16
#define HH 128
#define LL 3
#define BM 128
#define BK 16
#define EMW 132  // padded row stride (floats)

__device__ float g_h[(size_t)NN * HH];
__device__ float g_pa[(size_t)NN * HH];
__device__ float g_pb[(size_t)NN * HH];
__device__ float g_aggr[(size_t)NN * HH];
__device__ float g_wec[LL * EDIM * HH];
__device__ float g_b1e[LL * HH];
__device__ float g_w2frag[LL * 32768];    // fragment-packed hi/lo mW2
__device__ float g_uw2frag[LL * 32768];   // fragment-packed hi/lo uW2
__device__ int   g_src[EE];
__device__ int   g_dst[EE];
__device__ int   g_batchv[NN];
__device__ float g_pooled[BBATCH * HH];
__device__ float g_counts[BBATCH];

__device__ __forceinline__ float tf32r(float v) {
    uint32_t u;
    asm("cvt.rna.tf32.f32 %0, %1;" : "=r"(u) : "f"(v));
    return __uint_as_float(u);
}
__device__ __forceinline__ void mma8(float* c, const uint32_t* a, uint32_t b0, uint32_t b1) {
    asm volatile(
        "mma.sync.aligned.m16n8k8.row.col.f32.tf32.tf32.f32 "
        "{%0,%1,%2,%3}, {%4,%5,%6,%7}, {%8,%9}, {%0,%1,%2,%3};"
        : "+f"(c[0]), "+f"(c[1]), "+f"(c[2]), "+f"(c[3])
        : "r"(a[0]), "r"(a[1]), "r"(a[2]), "r"(a[3]), "r"(b0), "r"(b1));
}

// ---- convert with inline dtype detection ----
__global__ void convert_kernel(const unsigned int* __restrict__ eiu,
                               const void* __restrict__ bt) {
    int is64 = 1;
#pragma unroll
    for (int s = 0; s < 16; s++)
        if (eiu[2 * s + 1] != 0u) { is64 = 0; break; }
    const void* ei = (const void*)eiu;
    int i = blockIdx.x * blockDim.x + threadIdx.x;
    int stride = gridDim.x * blockDim.x;
    for (int k = i; k < EE; k += stride) {
        if (is64) {
            g_src[k] = (int)((const long long*)ei)[k];
            g_dst[k] = (int)((const long long*)ei)[EE + k];
        } else {
            g_src[k] = ((const int*)ei)[k];
            g_dst[k] = ((const int*)ei)[EE + k];
        }
    }
    for (int k = i; k < NN; k += stride)
        g_batchv[k] = is64 ? (int)((const long long*)bt)[k] : ((const int*)bt)[k];
}

__global__ void node_embed_kernel(const float* __restrict__ x,
                                  const float* __restrict__ Wn,
                                  const float* __restrict__ bn) {
    __shared__ float sW[NDIM * HH];
    __shared__ float sb[HH];
    for (int i = threadIdx.x; i < NDIM * HH; i += blockDim.x) sW[i] = Wn[i];
    if (threadIdx.x < HH) sb[threadIdx.x] = bn[threadIdx.x];
    __syncthreads();
    int g = blockIdx.x * blockDim.x + threadIdx.x;
    int stride = gridDim.x * blockDim.x;
    const int total = NN * 32;
    for (; g < total; g += stride) {
        int n = g >> 5;
        int c = (g & 31) * 4;
        const float* xr = x + (size_t)n * NDIM;
        float4 o = make_float4(sb[c], sb[c + 1], sb[c + 2], sb[c + 3]);
#pragma unroll
        for (int k = 0; k < NDIM; k++) {
            float a = __ldg(xr + k);
            float4 w = *(const float4*)&sW[k * HH + c];
            o.x = fmaf(a, w.x, o.x); o.y = fmaf(a, w.y, o.y);
            o.z = fmaf(a, w.z, o.z); o.w = fmaf(a, w.w, o.w);
        }
        *(float4*)&g_h[(size_t)n * HH + c] = o;
    }
}

// ---- unified weight prep: grid (LL, 49), block 512 ----
// y<17: Wec/b1e fuse (128 active).  17<=y<33: mW2 frags.  33<=y<49: uW2 frags.
__global__ void prep_kernel(const float* __restrict__ We, const float* __restrict__ be,
                            const float* __restrict__ mW1, const float* __restrict__ mb1,
                            const float* __restrict__ mW2, const float* __restrict__ uW2) {
    const int l = blockIdx.x, y = blockIdx.y;
    const int t = threadIdx.x;
    if (y < 17) {
        __shared__ float srow[HH];
        const float* W1c = mW1 + (size_t)l * 3 * HH * HH + 2 * HH * HH;
        const int d = y, c = t;
        if (t < HH) srow[c] = (d < EDIM) ? We[d * HH + c] : be[c];
        __syncthreads();
        if (t < HH) {
            float s = (d < EDIM) ? 0.f : mb1[l * HH + c];
            for (int j = 0; j < HH; j++)
                s = fmaf(srow[j], W1c[j * HH + c], s);
            if (d < EDIM) g_wec[(size_t)l * EDIM * HH + d * HH + c] = s;
            else          g_b1e[l * HH + c] = s;
        }
    } else {
        const int kc = (y - 17) & 15;
        const float* W = (y < 33) ? (mW2 + (size_t)l * HH * HH) : (uW2 + (size_t)l * HH * HH);
        float* outp = (y < 33) ? g_w2frag : g_uw2frag;
        const int nt = t >> 5, lane = t & 31;
        const int kr0 = kc * 8 + (lane & 3);
        const int col = nt * 8 + (lane >> 2);
        float b0 = W[kr0 * HH + col];
        float b1 = W[(kr0 + 4) * HH + col];
        float b0h = tf32r(b0), b1h = tf32r(b1);
        float4 v = make_float4(b0h, b1h, tf32r(b0 - b0h), tf32r(b1 - b1h));
        ((float4*)outp)[((size_t)l * 256 + kc * 16 + nt) * 32 + lane] = v;
    }
}

__global__ __launch_bounds__(256)
void pa_pb_kernel(const float* __restrict__ W1) {
    __shared__ float sA[BK * BM];
    __shared__ float sB[BK * HH];
    const int tid = threadIdx.x;
    const int nbase = blockIdx.x * BM;
    const int tx = tid & 15;
    const int ty = tid >> 4;
    const int r_g = tid >> 1;
    const int kq = (tid & 1) * 8;
    int gnode = nbase + r_g;
    if (gnode >= NN) gnode = NN - 1;
    const float* bp = g_h + (size_t)gnode * HH;
    const float* wb = W1 + (size_t)blockIdx.y * HH * HH;
    float* outp = blockIdx.y ? g_pb : g_pa;

    float acc[8][8];
#pragma unroll
    for (int i = 0; i < 8; i++)
#pragma unroll
        for (int j = 0; j < 8; j++) acc[i][j] = 0.f;
    const int wkr = (tid * 2) >> 5;
    const int wc4 = ((tid * 2) & 31) * 4;

#pragma unroll 1
    for (int kt = 0; kt < HH; kt += BK) {
        float4 v0 = *(const float4*)(bp + kt + kq);
        float4 v1 = *(const float4*)(bp + kt + kq + 4);
        sA[(kq + 0) * BM + r_g] = v0.x; sA[(kq + 1) * BM + r_g] = v0.y;
        sA[(kq + 2) * BM + r_g] = v0.z; sA[(kq + 3) * BM + r_g] = v0.w;
        sA[(kq + 4) * BM + r_g] = v1.x; sA[(kq + 5) * BM + r_g] = v1.y;
        sA[(kq + 6) * BM + r_g] = v1.z; sA[(kq + 7) * BM + r_g] = v1.w;
        const float* wp = wb + (size_t)(kt + wkr) * HH + wc4;
        *(float4*)&sB[wkr * HH + wc4]     = *(const float4*)wp;
        *(float4*)&sB[wkr * HH + wc4 + 4] = *(const float4*)(wp + 4);
        __syncthreads();
#pragma unroll
        for (int k = 0; k < BK; k++) {
            float4 a0 = *(float4*)&sA[k * BM + ty * 4];
            float4 a1 = *(float4*)&sA[k * BM + 64 + ty * 4];
            float4 bb0 = *(float4*)&sB[k * HH + tx * 4];
            float4 bb1 = *(float4*)&sB[k * HH + 64 + tx * 4];
            float a[8] = {a0.x, a0.y, a0.z, a0.w, a1.x, a1.y, a1.z, a1.w};
            float b[8] = {bb0.x, bb0.y, bb0.z, bb0.w, bb1.x, bb1.y, bb1.z, bb1.w};
#pragma unroll
            for (int i = 0; i < 8; i++)
#pragma unroll
                for (int j = 0; j < 8; j++)
                    acc[i][j] = fmaf(a[i], b[j], acc[i][j]);
        }
        __syncthreads();
    }
#pragma unroll
    for (int i = 0; i < 8; i++) {
        int r = (i < 4) ? (ty * 4 + i) : (64 + ty * 4 + (i - 4));
        int node = nbase + r;
        if (node < NN) {
            float* op = outp + (size_t)node * HH;
            *(float4*)(op + tx * 4) = make_float4(acc[i][0], acc[i][1], acc[i][2], acc[i][3]);
            *(float4*)(op + 64 + tx * 4) = make_float4(acc[i][4], acc[i][5], acc[i][6], acc[i][7]);
        }
    }
}

__global__ void zero_aggr_kernel() {
    int i = blockIdx.x * blockDim.x + threadIdx.x;
    int stride = gridDim.x * blockDim.x;
    float4 z = make_float4(0.f, 0.f, 0.f, 0.f);
    const int n4 = NN * HH / 4;
    for (int k = i; k < n4; k += stride) ((float4*)g_aggr)[k] = z;
}

__global__ void zero_pool_kernel() {
    for (int k = threadIdx.x; k < BBATCH * HH; k += blockDim.x) g_pooled[k] = 0.f;
    if (threadIdx.x < BBATCH) g_counts[threadIdx.x] = 0.f;
}

// ---- edge MLP: FFMA phase-1 + mma.sync tf32x3 phase-2 (W2 frags via L1/L2) ----
#define SH_F   0
#define SEA_F  (128 * EMW)
#define SWEC_F (SEA_F + 2048)
#define SB1E_F (SWEC_F + 2048)
#define SB2_F  (SB1E_F + 128)
#define IDX_F  (SB2_F + 128)
#define EK5_BYTES ((IDX_F + 256) * 4)

__global__ __launch_bounds__(256, 2)
void edge_mlp5_kernel(const float* __restrict__ ea, int l,
                      const float* __restrict__ b2v) {
    extern __shared__ float sm[];
    float* sH = sm + SH_F;
    float* sEA = sm + SEA_F;
    float* sWec = sm + SWEC_F;
    float* sB1e = sm + SB1E_F;
    float* sB2 = sm + SB2_F;
    int* sDst = (int*)(sm + IDX_F);
    int* sSrc = sDst + BM;

    const int tid = threadIdx.x;
    const int ebase = blockIdx.x * BM;

    if (tid < BM) sDst[tid] = g_dst[ebase + tid];
    else          sSrc[tid - BM] = g_src[ebase + tid - BM];
    {
        const float4* s4 = (const float4*)(ea + (size_t)ebase * EDIM);
        ((float4*)sEA)[tid] = s4[tid];
        ((float4*)sEA)[tid + 256] = s4[tid + 256];
        const float4* w4 = (const float4*)(g_wec + (size_t)l * EDIM * HH);
        ((float4*)sWec)[tid] = w4[tid];
        ((float4*)sWec)[tid + 256] = w4[tid + 256];
    }
    if (tid < HH) {
        sB1e[tid] = g_b1e[l * HH + tid];
        sB2[tid] = b2v[tid];
    }
    __syncthreads();

    // phase 1
    {
        const int r = tid >> 1;
        const int cb = (tid & 1) * 64;
        const float* pa = g_pa + (size_t)sDst[r] * HH + cb;
        const float* pb = g_pb + (size_t)sSrc[r] * HH + cb;
        float eav[16];
#pragma unroll
        for (int k = 0; k < 16; k++) eav[k] = sEA[r * EDIM + k];
#pragma unroll 4
        for (int c0 = 0; c0 < 64; c0 += 4) {
            float4 a = *(const float4*)(pa + c0);
            float4 b = *(const float4*)(pb + c0);
            float4 bb = *(const float4*)(sB1e + cb + c0);
            float sx = a.x + b.x + bb.x;
            float sy = a.y + b.y + bb.y;
            float sz = a.z + b.z + bb.z;
            float sw = a.w + b.w + bb.w;
#pragma unroll
            for (int k = 0; k < 16; k++) {
                float4 w = *(const float4*)&sWec[k * HH + cb + c0];
                sx = fmaf(eav[k], w.x, sx);
                sy = fmaf(eav[k], w.y, sy);
                sz = fmaf(eav[k], w.z, sz);
                sw = fmaf(eav[k], w.w, sw);
            }
            float4 o;
            o.x = fmaxf(sx, 0.f); o.y = fmaxf(sy, 0.f);
            o.z = fmaxf(sz, 0.f); o.w = fmaxf(sw, 0.f);
            *(float4*)&sH[r * EMW + cb + c0] = o;
        }
    }
    __syncthreads();

    // phase 2
    const int lane = tid & 31;
    const int wid = tid >> 5;
    const int r0 = wid * 16 + (lane >> 2);

    float acc[16][4];
#pragma unroll
    for (int nt = 0; nt < 16; nt++)
#pragma unroll
        for (int q = 0; q < 4; q++) acc[nt][q] = 0.f;

    const float4* w4 = (const float4*)(g_w2frag + (size_t)l * 32768);
#pragma unroll 1
    for (int kc = 0; kc < 16; kc++) {
        const int k0 = kc * 8 + (lane & 3);
        float a0 = sH[r0 * EMW + k0];
        float a1 = sH[(r0 + 8) * EMW + k0];
        float a2 = sH[r0 * EMW + k0 + 4];
        float a3 = sH[(r0 + 8) * EMW + k0 + 4];
        float h0 = tf32r(a0), h1 = tf32r(a1), h2 = tf32r(a2), h3 = tf32r(a3);
        uint32_t ah[4] = {__float_as_uint(h0), __float_as_uint(h1),
                          __float_as_uint(h2), __float_as_uint(h3)};
        uint32_t al[4] = {__float_as_uint(tf32r(a0 - h0)), __float_as_uint(tf32r(a1 - h1)),
                          __float_as_uint(tf32r(a2 - h2)), __float_as_uint(tf32r(a3 - h3))};
#pragma unroll
        for (int nt = 0; nt < 16; nt++) {
            float4 bq = __ldg(&w4[(kc * 16 + nt) * 32 + lane]);
            uint32_t bh0 = __float_as_uint(bq.x), bh1 = __float_as_uint(bq.y);
            uint32_t bl0 = __float_as_uint(bq.z), bl1 = __float_as_uint(bq.w);
            mma8(acc[nt], ah, bh0, bh1);
            mma8(acc[nt], al, bh0, bh1);
            mma8(acc[nt], ah, bl0, bl1);
        }
    }
    __syncthreads();

#pragma unroll
    for (int nt = 0; nt < 16; nt++) {
        int c = nt * 8 + 2 * (lane & 3);
        *(float2*)&sH[r0 * EMW + c] = make_float2(acc[nt][0], acc[nt][1]);
        *(float2*)&sH[(r0 + 8) * EMW + c] = make_float2(acc[nt][2], acc[nt][3]);
    }
    __syncthreads();

    {
        const int rr = tid >> 1;
        const int hb = (tid & 1) * 64;
        float* op = g_aggr + (size_t)sDst[rr] * HH + hb;
        const float* hrow = sH + rr * EMW + hb;
        const float* b2 = sB2 + hb;
#pragma unroll
        for (int c = 0; c < 64; c += 4) {
            float4 v = *(const float4*)(hrow + c);
            float4 b = *(const float4*)(b2 + c);
            float vx = v.x + b.x, vy = v.y + b.y, vz = v.z + b.z, vw = v.w + b.w;
            asm volatile("red.global.add.v4.f32 [%0], {%1, %2, %3, %4};"
                         :: "l"(op + c), "f"(vx), "f"(vy), "f"(vz), "f"(vw)
                         : "memory");
        }
    }
}

// ---- node update v2: FFMA W1 (K=256) + mma.sync tf32x3 for hidden@uW2 ----
#define NM_SA_F (128 * EMW)
#define NM_SB_F (NM_SA_F + BK * BM)
#define NM_BYTES ((NM_SB_F + BK * HH) * 4)

__global__ __launch_bounds__(256, 2)
void node_mlp2_kernel(const float* __restrict__ W1, const float* __restrict__ b1v,
                      int l, const float* __restrict__ b2v) {
    extern __shared__ float nsm[];
    float* sH = nsm;                 // 128 x EMW row-major hidden / D
    float* sA = nsm + NM_SA_F;
    float* sB = nsm + NM_SB_F;
    const int tid = threadIdx.x;
    const int nbase = blockIdx.x * BM;
    const int tx = tid & 15;
    const int ty = tid >> 4;
    const int r_g = tid >> 1;
    const int kq = (tid & 1) * 8;
    int gnode = nbase + r_g;
    if (gnode >= NN) gnode = NN - 1;
    const float* base0 = g_h + (size_t)gnode * HH;
    const float* base1 = g_aggr + (size_t)gnode * HH;

    float acc[8][8];
#pragma unroll
    for (int i = 0; i < 8; i++)
#pragma unroll
        for (int j = 0; j < 8; j++) acc[i][j] = 0.f;
    const int wkr = (tid * 2) >> 5;
    const int wc4 = ((tid * 2) & 31) * 4;

#pragma unroll 1
    for (int reg = 0; reg < 2; reg++) {
        const float* bp = (reg == 0) ? base0 : base1;
        const float* wb = W1 + (size_t)reg * HH * HH;
#pragma unroll 1
        for (int kt = 0; kt < HH; kt += BK) {
            float4 v0 = *(const float4*)(bp + kt + kq);
            float4 v1 = *(const float4*)(bp + kt + kq + 4);
            sA[(kq + 0) * BM + r_g] = v0.x; sA[(kq + 1) * BM + r_g] = v0.y;
            sA[(kq + 2) * BM + r_g] = v0.z; sA[(kq + 3) * BM + r_g] = v0.w;
            sA[(kq + 4) * BM + r_g] = v1.x; sA[(kq + 5) * BM + r_g] = v1.y;
            sA[(kq + 6) * BM + r_g] = v1.z; sA[(kq + 7) * BM + r_g] = v1.w;
            const float* wp = wb + (size_t)(kt + wkr) * HH + wc4;
            *(float4*)&sB[wkr * HH + wc4]     = *(const float4*)wp;
            *(float4*)&sB[wkr * HH + wc4 + 4] = *(const float4*)(wp + 4);
            __syncthreads();
#pragma unroll
            for (int k = 0; k < BK; k++) {
                float4 a0 = *(float4*)&sA[k * BM + ty * 4];
                float4 a1 = *(float4*)&sA[k * BM + 64 + ty * 4];
                float4 bb0 = *(float4*)&sB[k * HH + tx * 4];
                float4 bb1 = *(float4*)&sB[k * HH + 64 + tx * 4];
                float a[8] = {a0.x, a0.y, a0.z, a0.w, a1.x, a1.y, a1.z, a1.w};
                float b[8] = {bb0.x, bb0.y, bb0.z, bb0.w, bb1.x, bb1.y, bb1.z, bb1.w};
#pragma unroll
                for (int i = 0; i < 8; i++)
#pragma unroll
                    for (int j = 0; j < 8; j++)
                        acc[i][j] = fmaf(a[i], b[j], acc[i][j]);
            }
            __syncthreads();
        }
    }

    // hidden = relu(acc + b1) -> sH row-major
    {
        float4 bA = __ldg((const float4*)(b1v + tx * 4));
        float4 bB = __ldg((const float4*)(b1v + 64 + tx * 4));
#pragma unroll
        for (int i = 0; i < 8; i++) {
            int r = (i < 4) ? (ty * 4 + i) : (64 + ty * 4 + (i - 4));
            float4 v0, v1;
            v0.x = fmaxf(acc[i][0] + bA.x, 0.f);
            v0.y = fmaxf(acc[i][1] + bA.y, 0.f);
            v0.z = fmaxf(acc[i][2] + bA.z, 0.f);
            v0.w = fmaxf(acc[i][3] + bA.w, 0.f);
            v1.x = fmaxf(acc[i][4] + bB.x, 0.f);
            v1.y = fmaxf(acc[i][5] + bB.y, 0.f);
            v1.z = fmaxf(acc[i][6] + bB.z, 0.f);
            v1.w = fmaxf(acc[i][7] + bB.w, 0.f);
            *(float4*)&sH[r * EMW + tx * 4] = v0;
            *(float4*)&sH[r * EMW + 64 + tx * 4] = v1;
        }
    }
    __syncthreads();

    // phase 2: D = hidden @ uW2 via tf32x3 mma.sync
    const int lane = tid & 31;
    const int wid = tid >> 5;
    const int r0 = wid * 16 + (lane >> 2);

    float acc2[16][4];
#pragma unroll
    for (int nt = 0; nt < 16; nt++)
#pragma unroll
        for (int q = 0; q < 4; q++) acc2[nt][q] = 0.f;

    const float4* w4 = (const float4*)(g_uw2frag + (size_t)l * 32768);
#pragma unroll 1
    for (int kc = 0; kc < 16; kc++) {
        const int k0 = kc * 8 + (lane & 3);
        float a0 = sH[r0 * EMW + k0];
        float a1 = sH[(r0 + 8) * EMW + k0];
        float a2 = sH[r0 * EMW + k0 + 4];
        float a3 = sH[(r0 + 8) * EMW + k0 + 4];
        float h0 = tf32r(a0), h1 = tf32r(a1), h2 = tf32r(a2), h3 = tf32r(a3);
        uint32_t ah[4] = {__float_as_uint(h0), __float_as_uint(h1),
                          __float_as_uint(h2), __float_as_uint(h3)};
        uint32_t al[4] = {__float_as_uint(tf32r(a0 - h0)), __float_as_uint(tf32r(a1 - h1)),
                          __float_as_uint(tf32r(a2 - h2)), __float_as_uint(tf32r(a3 - h3))};
#pragma unroll
        for (int nt = 0; nt < 16; nt++) {
            float4 bq = __ldg(&w4[(kc * 16 + nt) * 32 + lane]);
            uint32_t bh0 = __float_as_uint(bq.x), bh1 = __float_as_uint(bq.y);
            uint32_t bl0 = __float_as_uint(bq.z), bl1 = __float_as_uint(bq.w);
            mma8(acc2[nt], ah, bh0, bh1);
            mma8(acc2[nt], al, bh0, bh1);
            mma8(acc2[nt], ah, bl0, bl1);
        }
    }
    __syncthreads();

#pragma unroll
    for (int nt = 0; nt < 16; nt++) {
        int c = nt * 8 + 2 * (lane & 3);
        *(float2*)&sH[r0 * EMW + c] = make_float2(acc2[nt][0], acc2[nt][1]);
        *(float2*)&sH[(r0 + 8) * EMW + c] = make_float2(acc2[nt][2], acc2[nt][3]);
    }
    __syncthreads();

    // residual: h += D + b2
    {
        const int rr = tid >> 1;
        const int hb = (tid & 1) * 64;
        int node = nbase + rr;
        if (node < NN) {
            float* op = g_h + (size_t)node * HH + hb;
            const float* hrow = sH + rr * EMW + hb;
#pragma unroll
            for (int c = 0; c < 64; c += 4) {
                float4 v = *(const float4*)(hrow + c);
                float4 b = __ldg((const float4*)(b2v + hb + c));
                float4 o = *(float4*)(op + c);
                o.x += v.x + b.x; o.y += v.y + b.y;
                o.z += v.z + b.z; o.w += v.w + b.w;
                *(float4*)(op + c) = o;
            }
        }
    }
}

__global__ void pool_kernel() {
    __shared__ float sp[BBATCH * HH];
    __shared__ float sc[BBATCH];
    for (int i = threadIdx.x; i < BBATCH * HH; i += blockDim.x) sp[i] = 0.f;
    if (threadIdx.x < BBATCH) sc[threadIdx.x] = 0.f;
    __syncthreads();
    int g = blockIdx.x * blockDim.x + threadIdx.x;
    int stride = gridDim.x * blockDim.x;
    const int total = NN * HH;
    for (int idx = g; idx < total; idx += stride) {
        int n = idx >> 7;
        int j = idx & 127;
        int b = g_batchv[n];
        atomicAdd(&sp[b * HH + j], g_h[idx]);
        if (j == 0) atomicAdd(&sc[b], 1.f);
    }
    __syncthreads();
    for (int i = threadIdx.x; i < BBATCH * HH; i += blockDim.x)
        atomicAdd(&g_pooled[i], sp[i]);
    if (threadIdx.x < BBATCH) atomicAdd(&g_counts[threadIdx.x], sc[threadIdx.x]);
}

__global__ void readout_kernel(const float* __restrict__ gf,
                               const float* __restrict__ Wg, const float* __restrict__ bg,
                               const float* __restrict__ rW1, const float* __restrict__ rb1,
                               const float* __restrict__ rW2, const float* __restrict__ rb2,
                               const float* __restrict__ rW3, const float* __restrict__ rb3,
                               float* __restrict__ out) {
    __shared__ float fin[BBATCH * 2 * HH];
    __shared__ float h1[BBATCH * HH];
    __shared__ float h2[BBATCH * 64];
    const int t = threadIdx.x;
    for (int idx = t; idx < BBATCH * 2 * HH; idx += blockDim.x) {
        int b = idx >> 8;
        int c = idx & 255;
        float v;
        if (c < HH) {
            float cnt = g_counts[b];
            if (cnt < 1.f) cnt = 1.f;
            v = g_pooled[b * HH + c] / cnt;
        } else {
            v = gf[b] * Wg[c - HH] + bg[c - HH];
        }
        fin[idx] = v;
    }
    __syncthreads();
    for (int idx = t; idx < BBATCH * HH; idx += blockDim.x) {
        int b = idx >> 7;
        int j = idx & 127;
        float s = rb1[j];
        for (int k = 0; k < 2 * HH; k++)
            s = fmaf(fin[b * 256 + k], rW1[k * HH + j], s);
        h1[idx] = (s > 0.f) ? s : 0.f;
    }
    __syncthreads();
    for (int idx = t; idx < BBATCH * 64; idx += blockDim.x) {
        int b = idx >> 6;
        int j = idx & 63;
        float s = rb2[j];
        for (int k = 0; k < HH; k++)
            s = fmaf(h1[b * HH + k], rW2[k * 64 + j], s);
        h2[idx] = (s > 0.f) ? s : 0.f;
    }
    __syncthreads();
    if (t < BBATCH) {
        float s = rb3[0];
        for (int k = 0; k < 64; k++)
            s = fmaf(h2[t * 64 + k], rW3[k], s);
        out[t] = s;
    }
}

// ---- host launcher ----
extern "C" void kernel_launch(void* const* d_in, const int* in_sizes, int n_in,
                              void* d_out, int out_size) {
    const float *x = 0, *ea = 0, *gf = 0;
    const void  *ei = 0, *bt = 0;
    const float *Wn = 0, *bn = 0, *We = 0, *be = 0, *Wg = 0, *bg = 0;
    const float *mW1 = 0, *mb1 = 0, *mW2 = 0, *mb2 = 0;
    const float *uW1 = 0, *ub1 = 0, *uW2 = 0, *ub2 = 0;
    const float *rW1 = 0, *rb1 = 0, *rW2 = 0, *rb2 = 0, *rW3 = 0, *rb3 = 0;
    int c128 = 0, c384 = 0, c49 = 0, c64 = 0;
    for (int i = 0; i < n_in; i++) {
        const void* p = d_in[i];
        switch (in_sizes[i]) {
            case 1600000: x = (const float*)p; break;
            case 6400000: ea = (const float*)p; break;
            case 8:       gf = (const float*)p; break;
            case 800000:  ei = p; break;
            case 50000:   bt = p; break;
            case 4096:    Wn = (const float*)p; break;
            case 2048:    We = (const float*)p; break;
            case 147456:  mW1 = (const float*)p; break;
            case 98304:   uW1 = (const float*)p; break;
            case 32768:   rW1 = (const float*)p; break;
            case 8192:    rW2 = (const float*)p; break;
            case 1:       rb3 = (const float*)p; break;
            case 128:
                if (c128 == 0) bn = (const float*)p;
                else if (c128 == 1) be = (const float*)p;
                else if (c128 == 2) Wg = (const float*)p;
                else if (c128 == 3) bg = (const float*)p;
                else rb1 = (const float*)p;
                c128++;
                break;
            case 384:
                if (c384 == 0) mb1 = (const float*)p;
                else if (c384 == 1) mb2 = (const float*)p;
                else if (c384 == 2) ub1 = (const float*)p;
                else ub2 = (const float*)p;
                c384++;
                break;
            case 49152:
                if (c49 == 0) mW2 = (const float*)p;
                else uW2 = (const float*)p;
                c49++;
                break;
            case 64:
                if (c64 == 0) rb2 = (const float*)p;
                else rW3 = (const float*)p;
                c64++;
                break;
            default: break;
        }
    }
    float* out = (float*)d_out;
    (void)out_size;

    cudaFuncSetAttribute(edge_mlp5_kernel, cudaFuncAttributeMaxDynamicSharedMemorySize, EK5_BYTES);
    cudaFuncSetAttribute(node_mlp2_kernel, cudaFuncAttributeMaxDynamicSharedMemorySize, NM_BYTES);

    const int NB_NODE = (NN + BM - 1) / BM;

    // launch order: convert(0) node_embed(1) prep(2) zero(3) pa_pb(4) edge(5) ...
    convert_kernel<<<1024, 256>>>((const unsigned int*)ei, bt);
    node_embed_kernel<<<3200, 256>>>(x, Wn, bn);
    prep_kernel<<<dim3(LL, 49), 512>>>(We, be, mW1, mb1, mW2, uW2);

    for (int l = 0; l < LL; l++) {
        zero_aggr_kernel<<<1600, 256>>>();
        pa_pb_kernel<<<dim3(NB_NODE, 2), 256>>>(mW1 + (size_t)l * 3 * HH * HH);
        edge_mlp5_kernel<<<EE / BM, 256, EK5_BYTES>>>(ea, l, mb2 + l * HH);
        node_mlp2_kernel<<<NB_NODE, 256, NM_BYTES>>>(
            uW1 + (size_t)l * 2 * HH * HH, ub1 + l * HH, l, ub2 + l * HH);
    }

    zero_pool_kernel<<<1, 256>>>();
    pool_kernel<<<1024, 256>>>();
    readout_kernel<<<1, 256>>>(gf, Wg, bg, rW1, rb1, rW2, rb2, rW3, rb3, out);
}

// round 16
// speedup vs baseline: 1.4658x; 1.4658x over previous
#include <cuda_runtime.h>
#include <cstdint>

#define NN 50000
#define EE 400000
#define BBATCH 8
#define NDIM 32
#define EDIM 16
#define HH 128
#define LL 3
#define BM 128
#define BK 16
#define EMW 132  // padded row stride (floats)

__device__ float g_h[(size_t)NN * HH];
__device__ float g_pa[(size_t)NN * HH];
__device__ float g_pb[(size_t)NN * HH];
__device__ float g_S[(size_t)NN * HH];        // scatter-sum of hidden
__device__ float g_deg[NN];
__device__ float g_wec[LL * EDIM * HH];
__device__ float g_b1e[LL * HH];
__device__ float g_wf[LL * HH * HH];          // mW2 @ uW1b
__device__ float g_bf[LL * HH];               // mb2 @ uW1b
__device__ float g_uw2frag[LL * 32768];       // fragment-packed hi/lo uW2
__device__ int   g_src[EE];
__device__ int   g_dst[EE];
__device__ int   g_batchv[NN];
__device__ float g_pooled[BBATCH * HH];
__device__ float g_counts[BBATCH];

__device__ __forceinline__ float tf32r(float v) {
    uint32_t u;
    asm("cvt.rna.tf32.f32 %0, %1;" : "=r"(u) : "f"(v));
    return __uint_as_float(u);
}
__device__ __forceinline__ void mma8(float* c, const uint32_t* a, uint32_t b0, uint32_t b1) {
    asm volatile(
        "mma.sync.aligned.m16n8k8.row.col.f32.tf32.tf32.f32 "
        "{%0,%1,%2,%3}, {%4,%5,%6,%7}, {%8,%9}, {%0,%1,%2,%3};"
        : "+f"(c[0]), "+f"(c[1]), "+f"(c[2]), "+f"(c[3])
        : "r"(a[0]), "r"(a[1]), "r"(a[2]), "r"(a[3]), "r"(b0), "r"(b1));
}

// ---- zero deg/pool (every launch, before convert's deg atomics) ----
__global__ void zero_misc_kernel() {
    int i = blockIdx.x * blockDim.x + threadIdx.x;
    int stride = gridDim.x * blockDim.x;
    for (int k = i; k < NN; k += stride) g_deg[k] = 0.f;
    if (blockIdx.x == 0) {
        for (int k = threadIdx.x; k < BBATCH * HH; k += blockDim.x) g_pooled[k] = 0.f;
        if (threadIdx.x < BBATCH) g_counts[threadIdx.x] = 0.f;
    }
}

// ---- convert with inline dtype detection + deg count ----
__global__ void convert_kernel(const unsigned int* __restrict__ eiu,
                               const void* __restrict__ bt) {
    int is64 = 1;
#pragma unroll
    for (int s = 0; s < 16; s++)
        if (eiu[2 * s + 1] != 0u) { is64 = 0; break; }
    const void* ei = (const void*)eiu;
    int i = blockIdx.x * blockDim.x + threadIdx.x;
    int stride = gridDim.x * blockDim.x;
    for (int k = i; k < EE; k += stride) {
        int s, d;
        if (is64) {
            s = (int)((const long long*)ei)[k];
            d = (int)((const long long*)ei)[EE + k];
        } else {
            s = ((const int*)ei)[k];
            d = ((const int*)ei)[EE + k];
        }
        g_src[k] = s;
        g_dst[k] = d;
        atomicAdd(&g_deg[d], 1.f);
    }
    for (int k = i; k < NN; k += stride)
        g_batchv[k] = is64 ? (int)((const long long*)bt)[k] : ((const int*)bt)[k];
}

__global__ void node_embed_kernel(const float* __restrict__ x,
                                  const float* __restrict__ Wn,
                                  const float* __restrict__ bn) {
    __shared__ float sW[NDIM * HH];
    __shared__ float sb[HH];
    for (int i = threadIdx.x; i < NDIM * HH; i += blockDim.x) sW[i] = Wn[i];
    if (threadIdx.x < HH) sb[threadIdx.x] = bn[threadIdx.x];
    __syncthreads();
    int g = blockIdx.x * blockDim.x + threadIdx.x;
    int stride = gridDim.x * blockDim.x;
    const int total = NN * 32;
    for (; g < total; g += stride) {
        int n = g >> 5;
        int c = (g & 31) * 4;
        const float* xr = x + (size_t)n * NDIM;
        float4 o = make_float4(sb[c], sb[c + 1], sb[c + 2], sb[c + 3]);
#pragma unroll
        for (int k = 0; k < NDIM; k++) {
            float a = __ldg(xr + k);
            float4 w = *(const float4*)&sW[k * HH + c];
            o.x = fmaf(a, w.x, o.x); o.y = fmaf(a, w.y, o.y);
            o.z = fmaf(a, w.z, o.z); o.w = fmaf(a, w.w, o.w);
        }
        *(float4*)&g_h[(size_t)n * HH + c] = o;
    }
}

// ---- unified weight prep: grid (LL, 49), block 512 ----
// y<17: Wec/b1e (+bf at y==16).  17<=y<33: uW2 frags.  33<=y<49: Wf rows.
__global__ void prep_kernel(const float* __restrict__ We, const float* __restrict__ be,
                            const float* __restrict__ mW1, const float* __restrict__ mb1,
                            const float* __restrict__ mW2, const float* __restrict__ mb2,
                            const float* __restrict__ uW1, const float* __restrict__ uW2) {
    const int l = blockIdx.x, y = blockIdx.y;
    const int t = threadIdx.x;
    if (y < 17) {
        __shared__ float srow[HH];
        const float* W1c = mW1 + (size_t)l * 3 * HH * HH + 2 * HH * HH;
        if (t < HH) srow[t] = (y < EDIM) ? We[y * HH + t] : be[t];
        __syncthreads();
        if (t < HH) {
            float s = (y < EDIM) ? 0.f : mb1[l * HH + t];
            for (int j = 0; j < HH; j++)
                s = fmaf(srow[j], W1c[j * HH + t], s);
            if (y < EDIM) g_wec[(size_t)l * EDIM * HH + y * HH + t] = s;
            else          g_b1e[l * HH + t] = s;
        } else if (y == 16 && t < 256) {
            const int c = t - HH;
            const float* u1b = uW1 + (size_t)l * 2 * HH * HH + HH * HH;
            float s = 0.f;
            for (int n = 0; n < HH; n++)
                s = fmaf(mb2[l * HH + n], u1b[n * HH + c], s);
            g_bf[l * HH + c] = s;
        }
    } else if (y < 33) {
        const int kc = y - 17;
        const float* W = uW2 + (size_t)l * HH * HH;
        const int nt = t >> 5, lane = t & 31;
        const int kr0 = kc * 8 + (lane & 3);
        const int col = nt * 8 + (lane >> 2);
        float b0 = W[kr0 * HH + col];
        float b1 = W[(kr0 + 4) * HH + col];
        float b0h = tf32r(b0), b1h = tf32r(b1);
        float4 v = make_float4(b0h, b1h, tf32r(b0 - b0h), tf32r(b1 - b1h));
        ((float4*)g_uw2frag)[((size_t)l * 256 + kc * 16 + nt) * 32 + lane] = v;
    } else {
        // Wf[j][c] = sum_n mW2[j][n] * uW1b[n][c]; 8 rows per block
        const int j0 = (y - 33) * 8;
        const float* W2 = mW2 + (size_t)l * HH * HH;
        const float* u1b = uW1 + (size_t)l * 2 * HH * HH + HH * HH;
#pragma unroll 1
        for (int idx = t; idx < 8 * HH; idx += 512) {
            int j = j0 + (idx >> 7);
            int c = idx & 127;
            float s = 0.f;
            for (int n = 0; n < HH; n++)
                s = fmaf(__ldg(&W2[j * HH + n]), __ldg(&u1b[n * HH + c]), s);
            g_wf[(size_t)l * HH * HH + j * HH + c] = s;
        }
    }
}

__global__ __launch_bounds__(256)
void pa_pb_kernel(const float* __restrict__ W1) {
    __shared__ float sA[BK * BM];
    __shared__ float sB[BK * HH];
    const int tid = threadIdx.x;
    const int nbase = blockIdx.x * BM;
    const int tx = tid & 15;
    const int ty = tid >> 4;
    const int r_g = tid >> 1;
    const int kq = (tid & 1) * 8;
    int gnode = nbase + r_g;
    if (gnode >= NN) gnode = NN - 1;
    const float* bp = g_h + (size_t)gnode * HH;
    const float* wb = W1 + (size_t)blockIdx.y * HH * HH;
    float* outp = blockIdx.y ? g_pb : g_pa;

    float acc[8][8];
#pragma unroll
    for (int i = 0; i < 8; i++)
#pragma unroll
        for (int j = 0; j < 8; j++) acc[i][j] = 0.f;
    const int wkr = (tid * 2) >> 5;
    const int wc4 = ((tid * 2) & 31) * 4;

#pragma unroll 1
    for (int kt = 0; kt < HH; kt += BK) {
        float4 v0 = *(const float4*)(bp + kt + kq);
        float4 v1 = *(const float4*)(bp + kt + kq + 4);
        sA[(kq + 0) * BM + r_g] = v0.x; sA[(kq + 1) * BM + r_g] = v0.y;
        sA[(kq + 2) * BM + r_g] = v0.z; sA[(kq + 3) * BM + r_g] = v0.w;
        sA[(kq + 4) * BM + r_g] = v1.x; sA[(kq + 5) * BM + r_g] = v1.y;
        sA[(kq + 6) * BM + r_g] = v1.z; sA[(kq + 7) * BM + r_g] = v1.w;
        const float* wp = wb + (size_t)(kt + wkr) * HH + wc4;
        *(float4*)&sB[wkr * HH + wc4]     = *(const float4*)wp;
        *(float4*)&sB[wkr * HH + wc4 + 4] = *(const float4*)(wp + 4);
        __syncthreads();
#pragma unroll
        for (int k = 0; k < BK; k++) {
            float4 a0 = *(float4*)&sA[k * BM + ty * 4];
            float4 a1 = *(float4*)&sA[k * BM + 64 + ty * 4];
            float4 bb0 = *(float4*)&sB[k * HH + tx * 4];
            float4 bb1 = *(float4*)&sB[k * HH + 64 + tx * 4];
            float a[8] = {a0.x, a0.y, a0.z, a0.w, a1.x, a1.y, a1.z, a1.w};
            float b[8] = {bb0.x, bb0.y, bb0.z, bb0.w, bb1.x, bb1.y, bb1.z, bb1.w};
#pragma unroll
            for (int i = 0; i < 8; i++)
#pragma unroll
                for (int j = 0; j < 8; j++)
                    acc[i][j] = fmaf(a[i], b[j], acc[i][j]);
        }
        __syncthreads();
    }
#pragma unroll
    for (int i = 0; i < 8; i++) {
        int r = (i < 4) ? (ty * 4 + i) : (64 + ty * 4 + (i - 4));
        int node = nbase + r;
        if (node < NN) {
            float* op = outp + (size_t)node * HH;
            *(float4*)(op + tx * 4) = make_float4(acc[i][0], acc[i][1], acc[i][2], acc[i][3]);
            *(float4*)(op + 64 + tx * 4) = make_float4(acc[i][4], acc[i][5], acc[i][6], acc[i][7]);
        }
    }
}

__global__ void zero_S_kernel() {
    int i = blockIdx.x * blockDim.x + threadIdx.x;
    int stride = gridDim.x * blockDim.x;
    float4 z = make_float4(0.f, 0.f, 0.f, 0.f);
    const int n4 = NN * HH / 4;
    for (int k = i; k < n4; k += stride) ((float4*)g_S)[k] = z;
}

// ---- edge kernel v6: phase-1 only, register hidden, direct scatter of hidden ----
__global__ __launch_bounds__(256)
void edge_mlp6_kernel(const float* __restrict__ ea, int l) {
    __shared__ float sEA[2048];
    __shared__ float sWec[2048];
    __shared__ float sB1e[HH];
    __shared__ int sDst[BM];
    __shared__ int sSrc[BM];

    const int tid = threadIdx.x;
    const int ebase = blockIdx.x * BM;

    if (tid < BM) sDst[tid] = g_dst[ebase + tid];
    else          sSrc[tid - BM] = g_src[ebase + tid - BM];
    {
        const float4* s4 = (const float4*)(ea + (size_t)ebase * EDIM);
        ((float4*)sEA)[tid] = s4[tid];
        ((float4*)sEA)[tid + 256] = s4[tid + 256];
        const float4* w4 = (const float4*)(g_wec + (size_t)l * EDIM * HH);
        ((float4*)sWec)[tid] = w4[tid];
        ((float4*)sWec)[tid + 256] = w4[tid + 256];
    }
    if (tid < HH) sB1e[tid] = g_b1e[l * HH + tid];
    __syncthreads();

    const int r = tid >> 1;
    const int cb = (tid & 1) * 64;
    const int dst = sDst[r];
    const float* pa = g_pa + (size_t)dst * HH + cb;
    const float* pb = g_pb + (size_t)sSrc[r] * HH + cb;

    float4 s[16];
#pragma unroll
    for (int i = 0; i < 16; i++) {
        float4 a = *(const float4*)(pa + 4 * i);
        float4 b = *(const float4*)(pb + 4 * i);
        float4 bb = *(const float4*)(sB1e + cb + 4 * i);
        s[i].x = a.x + b.x + bb.x;
        s[i].y = a.y + b.y + bb.y;
        s[i].z = a.z + b.z + bb.z;
        s[i].w = a.w + b.w + bb.w;
    }
    float eav[16];
#pragma unroll
    for (int k = 0; k < 16; k++) eav[k] = sEA[r * EDIM + k];
#pragma unroll
    for (int k = 0; k < 16; k++) {
        float e = eav[k];
#pragma unroll
        for (int i = 0; i < 16; i++) {
            float4 w = *(const float4*)&sWec[k * HH + cb + 4 * i];
            s[i].x = fmaf(e, w.x, s[i].x);
            s[i].y = fmaf(e, w.y, s[i].y);
            s[i].z = fmaf(e, w.z, s[i].z);
            s[i].w = fmaf(e, w.w, s[i].w);
        }
    }
    float* op = g_S + (size_t)dst * HH + cb;
#pragma unroll
    for (int i = 0; i < 16; i++) {
        float vx = fmaxf(s[i].x, 0.f), vy = fmaxf(s[i].y, 0.f);
        float vz = fmaxf(s[i].z, 0.f), vw = fmaxf(s[i].w, 0.f);
        asm volatile("red.global.add.v4.f32 [%0], {%1, %2, %3, %4};"
                     :: "l"(op + 4 * i), "f"(vx), "f"(vy), "f"(vz), "f"(vw)
                     : "memory");
    }
}

// ---- node update v3: hidden = relu(h@uW1a + S@Wf + deg*bf + ub1); out via uW2 HMMA ----
#define NM_SA_F (128 * EMW)
#define NM_SB_F (NM_SA_F + BK * BM)
#define NM_BYTES ((NM_SB_F + BK * HH) * 4)

__global__ __launch_bounds__(256, 2)
void node_mlp3_kernel(const float* __restrict__ uW1, const float* __restrict__ b1v,
                      int l, const float* __restrict__ b2v) {
    extern __shared__ float nsm[];
    float* sH = nsm;
    float* sA = nsm + NM_SA_F;
    float* sB = nsm + NM_SB_F;
    const int tid = threadIdx.x;
    const int nbase = blockIdx.x * BM;
    const int tx = tid & 15;
    const int ty = tid >> 4;
    const int r_g = tid >> 1;
    const int kq = (tid & 1) * 8;
    int gnode = nbase + r_g;
    if (gnode >= NN) gnode = NN - 1;
    const float* base0 = g_h + (size_t)gnode * HH;
    const float* base1 = g_S + (size_t)gnode * HH;

    float acc[8][8];
#pragma unroll
    for (int i = 0; i < 8; i++)
#pragma unroll
        for (int j = 0; j < 8; j++) acc[i][j] = 0.f;
    const int wkr = (tid * 2) >> 5;
    const int wc4 = ((tid * 2) & 31) * 4;

#pragma unroll 1
    for (int reg = 0; reg < 2; reg++) {
        const float* bp = (reg == 0) ? base0 : base1;
        const float* wb = (reg == 0) ? uW1 : (g_wf + (size_t)l * HH * HH);
#pragma unroll 1
        for (int kt = 0; kt < HH; kt += BK) {
            float4 v0 = *(const float4*)(bp + kt + kq);
            float4 v1 = *(const float4*)(bp + kt + kq + 4);
            sA[(kq + 0) * BM + r_g] = v0.x; sA[(kq + 1) * BM + r_g] = v0.y;
            sA[(kq + 2) * BM + r_g] = v0.z; sA[(kq + 3) * BM + r_g] = v0.w;
            sA[(kq + 4) * BM + r_g] = v1.x; sA[(kq + 5) * BM + r_g] = v1.y;
            sA[(kq + 6) * BM + r_g] = v1.z; sA[(kq + 7) * BM + r_g] = v1.w;
            const float* wp = wb + (size_t)(kt + wkr) * HH + wc4;
            *(float4*)&sB[wkr * HH + wc4]     = *(const float4*)wp;
            *(float4*)&sB[wkr * HH + wc4 + 4] = *(const float4*)(wp + 4);
            __syncthreads();
#pragma unroll
            for (int k = 0; k < BK; k++) {
                float4 a0 = *(float4*)&sA[k * BM + ty * 4];
                float4 a1 = *(float4*)&sA[k * BM + 64 + ty * 4];
                float4 bb0 = *(float4*)&sB[k * HH + tx * 4];
                float4 bb1 = *(float4*)&sB[k * HH + 64 + tx * 4];
                float a[8] = {a0.x, a0.y, a0.z, a0.w, a1.x, a1.y, a1.z, a1.w};
                float b[8] = {bb0.x, bb0.y, bb0.z, bb0.w, bb1.x, bb1.y, bb1.z, bb1.w};
#pragma unroll
                for (int i = 0; i < 8; i++)
#pragma unroll
                    for (int j = 0; j < 8; j++)
                        acc[i][j] = fmaf(a[i], b[j], acc[i][j]);
            }
            __syncthreads();
        }
    }

    // hidden = relu(acc + ub1 + deg*bf) -> sH row-major
    {
        const float* bf = g_bf + l * HH;
        float4 bA = __ldg((const float4*)(b1v + tx * 4));
        float4 bB = __ldg((const float4*)(b1v + 64 + tx * 4));
        float4 fA = __ldg((const float4*)(bf + tx * 4));
        float4 fB = __ldg((const float4*)(bf + 64 + tx * 4));
#pragma unroll
        for (int i = 0; i < 8; i++) {
            int r = (i < 4) ? (ty * 4 + i) : (64 + ty * 4 + (i - 4));
            int node = nbase + r;
            float dg = g_deg[(node < NN) ? node : (NN - 1)];
            float4 v0, v1;
            v0.x = fmaxf(acc[i][0] + bA.x + dg * fA.x, 0.f);
            v0.y = fmaxf(acc[i][1] + bA.y + dg * fA.y, 0.f);
            v0.z = fmaxf(acc[i][2] + bA.z + dg * fA.z, 0.f);
            v0.w = fmaxf(acc[i][3] + bA.w + dg * fA.w, 0.f);
            v1.x = fmaxf(acc[i][4] + bB.x + dg * fB.x, 0.f);
            v1.y = fmaxf(acc[i][5] + bB.y + dg * fB.y, 0.f);
            v1.z = fmaxf(acc[i][6] + bB.z + dg * fB.z, 0.f);
            v1.w = fmaxf(acc[i][7] + bB.w + dg * fB.w, 0.f);
            *(float4*)&sH[r * EMW + tx * 4] = v0;
            *(float4*)&sH[r * EMW + 64 + tx * 4] = v1;
        }
    }
    __syncthreads();

    // phase 2: D = hidden @ uW2 via tf32x3 mma.sync
    const int lane = tid & 31;
    const int wid = tid >> 5;
    const int r0 = wid * 16 + (lane >> 2);

    float acc2[16][4];
#pragma unroll
    for (int nt = 0; nt < 16; nt++)
#pragma unroll
        for (int q = 0; q < 4; q++) acc2[nt][q] = 0.f;

    const float4* w4 = (const float4*)(g_uw2frag + (size_t)l * 32768);
#pragma unroll 1
    for (int kc = 0; kc < 16; kc++) {
        const int k0 = kc * 8 + (lane & 3);
        float a0 = sH[r0 * EMW + k0];
        float a1 = sH[(r0 + 8) * EMW + k0];
        float a2 = sH[r0 * EMW + k0 + 4];
        float a3 = sH[(r0 + 8) * EMW + k0 + 4];
        float h0 = tf32r(a0), h1 = tf32r(a1), h2 = tf32r(a2), h3 = tf32r(a3);
        uint32_t ah[4] = {__float_as_uint(h0), __float_as_uint(h1),
                          __float_as_uint(h2), __float_as_uint(h3)};
        uint32_t al[4] = {__float_as_uint(tf32r(a0 - h0)), __float_as_uint(tf32r(a1 - h1)),
                          __float_as_uint(tf32r(a2 - h2)), __float_as_uint(tf32r(a3 - h3))};
#pragma unroll
        for (int nt = 0; nt < 16; nt++) {
            float4 bq = __ldg(&w4[(kc * 16 + nt) * 32 + lane]);
            uint32_t bh0 = __float_as_uint(bq.x), bh1 = __float_as_uint(bq.y);
            uint32_t bl0 = __float_as_uint(bq.z), bl1 = __float_as_uint(bq.w);
            mma8(acc2[nt], ah, bh0, bh1);
            mma8(acc2[nt], al, bh0, bh1);
            mma8(acc2[nt], ah, bl0, bl1);
        }
    }
    __syncthreads();

#pragma unroll
    for (int nt = 0; nt < 16; nt++) {
        int c = nt * 8 + 2 * (lane & 3);
        *(float2*)&sH[r0 * EMW + c] = make_float2(acc2[nt][0], acc2[nt][1]);
        *(float2*)&sH[(r0 + 8) * EMW + c] = make_float2(acc2[nt][2], acc2[nt][3]);
    }
    __syncthreads();

    // residual: h += D + b2
    {
        const int rr = tid >> 1;
        const int hb = (tid & 1) * 64;
        int node = nbase + rr;
        if (node < NN) {
            float* op = g_h + (size_t)node * HH + hb;
            const float* hrow = sH + rr * EMW + hb;
#pragma unroll
            for (int c = 0; c < 64; c += 4) {
                float4 v = *(const float4*)(hrow + c);
                float4 b = __ldg((const float4*)(b2v + hb + c));
                float4 o = *(float4*)(op + c);
                o.x += v.x + b.x; o.y += v.y + b.y;
                o.z += v.z + b.z; o.w += v.w + b.w;
                *(float4*)(op + c) = o;
            }
        }
    }
}

__global__ void pool_kernel() {
    __shared__ float sp[BBATCH * HH];
    __shared__ float sc[BBATCH];
    for (int i = threadIdx.x; i < BBATCH * HH; i += blockDim.x) sp[i] = 0.f;
    if (threadIdx.x < BBATCH) sc[threadIdx.x] = 0.f;
    __syncthreads();
    int g = blockIdx.x * blockDim.x + threadIdx.x;
    int stride = gridDim.x * blockDim.x;
    const int total = NN * HH;
    for (int idx = g; idx < total; idx += stride) {
        int n = idx >> 7;
        int j = idx & 127;
        int b = g_batchv[n];
        atomicAdd(&sp[b * HH + j], g_h[idx]);
        if (j == 0) atomicAdd(&sc[b], 1.f);
    }
    __syncthreads();
    for (int i = threadIdx.x; i < BBATCH * HH; i += blockDim.x)
        atomicAdd(&g_pooled[i], sp[i]);
    if (threadIdx.x < BBATCH) atomicAdd(&g_counts[threadIdx.x], sc[threadIdx.x]);
}

__global__ void readout_kernel(const float* __restrict__ gf,
                               const float* __restrict__ Wg, const float* __restrict__ bg,
                               const float* __restrict__ rW1, const float* __restrict__ rb1,
                               const float* __restrict__ rW2, const float* __restrict__ rb2,
                               const float* __restrict__ rW3, const float* __restrict__ rb3,
                               float* __restrict__ out) {
    __shared__ float fin[BBATCH * 2 * HH];
    __shared__ float h1[BBATCH * HH];
    __shared__ float h2[BBATCH * 64];
    const int t = threadIdx.x;
    for (int idx = t; idx < BBATCH * 2 * HH; idx += blockDim.x) {
        int b = idx >> 8;
        int c = idx & 255;
        float v;
        if (c < HH) {
            float cnt = g_counts[b];
            if (cnt < 1.f) cnt = 1.f;
            v = g_pooled[b * HH + c] / cnt;
        } else {
            v = gf[b] * Wg[c - HH] + bg[c - HH];
        }
        fin[idx] = v;
    }
    __syncthreads();
    for (int idx = t; idx < BBATCH * HH; idx += blockDim.x) {
        int b = idx >> 7;
        int j = idx & 127;
        float s = rb1[j];
        for (int k = 0; k < 2 * HH; k++)
            s = fmaf(fin[b * 256 + k], rW1[k * HH + j], s);
        h1[idx] = (s > 0.f) ? s : 0.f;
    }
    __syncthreads();
    for (int idx = t; idx < BBATCH * 64; idx += blockDim.x) {
        int b = idx >> 6;
        int j = idx & 63;
        float s = rb2[j];
        for (int k = 0; k < HH; k++)
            s = fmaf(h1[b * HH + k], rW2[k * 64 + j], s);
        h2[idx] = (s > 0.f) ? s : 0.f;
    }
    __syncthreads();
    if (t < BBATCH) {
        float s = rb3[0];
        for (int k = 0; k < 64; k++)
            s = fmaf(h2[t * 64 + k], rW3[k], s);
        out[t] = s;
    }
}

// ---- host launcher ----
extern "C" void kernel_launch(void* const* d_in, const int* in_sizes, int n_in,
                              void* d_out, int out_size) {
    const float *x = 0, *ea = 0, *gf = 0;
    const void  *ei = 0, *bt = 0;
    const float *Wn = 0, *bn = 0, *We = 0, *be = 0, *Wg = 0, *bg = 0;
    const float *mW1 = 0, *mb1 = 0, *mW2 = 0, *mb2 = 0;
    const float *uW1 = 0, *ub1 = 0, *uW2 = 0, *ub2 = 0;
    const float *rW1 = 0, *rb1 = 0, *rW2 = 0, *rb2 = 0, *rW3 = 0, *rb3 = 0;
    int c128 = 0, c384 = 0, c49 = 0, c64 = 0;
    for (int i = 0; i < n_in; i++) {
        const void* p = d_in[i];
        switch (in_sizes[i]) {
            case 1600000: x = (const float*)p; break;
            case 6400000: ea = (const float*)p; break;
            case 8:       gf = (const float*)p; break;
            case 800000:  ei = p; break;
            case 50000:   bt = p; break;
            case 4096:    Wn = (const float*)p; break;
            case 2048:    We = (const float*)p; break;
            case 147456:  mW1 = (const float*)p; break;
            case 98304:   uW1 = (const float*)p; break;
            case 32768:   rW1 = (const float*)p; break;
            case 8192:    rW2 = (const float*)p; break;
            case 1:       rb3 = (const float*)p; break;
            case 128:
                if (c128 == 0) bn = (const float*)p;
                else if (c128 == 1) be = (const float*)p;
                else if (c128 == 2) Wg = (const float*)p;
                else if (c128 == 3) bg = (const float*)p;
                else rb1 = (const float*)p;
                c128++;
                break;
            case 384:
                if (c384 == 0) mb1 = (const float*)p;
                else if (c384 == 1) mb2 = (const float*)p;
                else if (c384 == 2) ub1 = (const float*)p;
                else ub2 = (const float*)p;
                c384++;
                break;
            case 49152:
                if (c49 == 0) mW2 = (const float*)p;
                else uW2 = (const float*)p;
                c49++;
                break;
            case 64:
                if (c64 == 0) rb2 = (const float*)p;
                else rW3 = (const float*)p;
                c64++;
                break;
            default: break;
        }
    }
    float* out = (float*)d_out;
    (void)out_size;

    cudaFuncSetAttribute(node_mlp3_kernel, cudaFuncAttributeMaxDynamicSharedMemorySize, NM_BYTES);

    const int NB_NODE = (NN + BM - 1) / BM;

    zero_misc_kernel<<<256, 256>>>();
    convert_kernel<<<1024, 256>>>((const unsigned int*)ei, bt);
    node_embed_kernel<<<3200, 256>>>(x, Wn, bn);
    prep_kernel<<<dim3(LL, 49), 512>>>(We, be, mW1, mb1, mW2, mb2, uW1, uW2);

    for (int l = 0; l < LL; l++) {
        zero_S_kernel<<<1600, 256>>>();
        pa_pb_kernel<<<dim3(NB_NODE, 2), 256>>>(mW1 + (size_t)l * 3 * HH * HH);
        edge_mlp6_kernel<<<EE / BM, 256>>>(ea, l);
        node_mlp3_kernel<<<NB_NODE, 256, NM_BYTES>>>(
            uW1 + (size_t)l * 2 * HH * HH, ub1 + l * HH, l, ub2 + l * HH);
    }

    zero_pool_kernel_dummy:;
    pool_kernel<<<1024, 256>>>();
    readout_kernel<<<1, 256>>>(gf, Wg, bg, rW1, rb1, rW2, rb2, rW3, rb3, out);
}

// round 17
// speedup vs baseline: 1.5060x; 1.0274x over previous
#include <cuda_runtime.h>
#include <cstdint>

#define NN 50000
#define EE 400000
#define BBATCH 8
#define NDIM 32
#define EDIM 16
#define HH 128
#define LL 3
#define BM 128
#define EMW 132  // padded row stride (floats)

__device__ float g_h[(size_t)NN * HH];
__device__ float g_pa[(size_t)NN * HH];
__device__ float g_pb[(size_t)NN * HH];
__device__ float g_S[(size_t)NN * HH];        // scatter-sum of hidden
__device__ float g_deg[NN];
__device__ float g_wec[LL * EDIM * HH];
__device__ float g_b1e[LL * HH];
__device__ float g_bf[LL * HH];               // mb2 @ uW1b
__device__ float g_uw2frag[LL * 32768];       // fragment-packed hi/lo uW2
__device__ float g_wffrag[LL * 32768];        // fragment-packed hi/lo (mW2@uW1b)
__device__ float g_w1afrag[LL * 32768];       // fragment-packed hi/lo W1a
__device__ float g_w1bfrag[LL * 32768];       // fragment-packed hi/lo W1b
__device__ float g_uw1afrag[LL * 32768];      // fragment-packed hi/lo uW1a
__device__ int   g_src[EE];
__device__ int   g_dst[EE];
__device__ int   g_batchv[NN];
__device__ float g_pooled[BBATCH * HH];
__device__ float g_counts[BBATCH];

__device__ __forceinline__ float tf32r(float v) {
    uint32_t u;
    asm("cvt.rna.tf32.f32 %0, %1;" : "=r"(u) : "f"(v));
    return __uint_as_float(u);
}
__device__ __forceinline__ void mma8(float* c, const uint32_t* a, uint32_t b0, uint32_t b1) {
    asm volatile(
        "mma.sync.aligned.m16n8k8.row.col.f32.tf32.tf32.f32 "
        "{%0,%1,%2,%3}, {%4,%5,%6,%7}, {%8,%9}, {%0,%1,%2,%3};"
        : "+f"(c[0]), "+f"(c[1]), "+f"(c[2]), "+f"(c[3])
        : "r"(a[0]), "r"(a[1]), "r"(a[2]), "r"(a[3]), "r"(b0), "r"(b1));
}

// One tf32x3 HMMA sweep: acc += sH(A rows r0,r0+8) @ Bfrags
__device__ __forceinline__ void hmma_sweep(const float* sH, const float4* w4,
                                           int r0, int lane, float acc[16][4]) {
#pragma unroll 1
    for (int kc = 0; kc < 16; kc++) {
        const int k0 = kc * 8 + (lane & 3);
        float a0 = sH[r0 * EMW + k0];
        float a1 = sH[(r0 + 8) * EMW + k0];
        float a2 = sH[r0 * EMW + k0 + 4];
        float a3 = sH[(r0 + 8) * EMW + k0 + 4];
        float h0 = tf32r(a0), h1 = tf32r(a1), h2 = tf32r(a2), h3 = tf32r(a3);
        uint32_t ah[4] = {__float_as_uint(h0), __float_as_uint(h1),
                          __float_as_uint(h2), __float_as_uint(h3)};
        uint32_t al[4] = {__float_as_uint(tf32r(a0 - h0)), __float_as_uint(tf32r(a1 - h1)),
                          __float_as_uint(tf32r(a2 - h2)), __float_as_uint(tf32r(a3 - h3))};
#pragma unroll
        for (int nt = 0; nt < 16; nt++) {
            float4 bq = __ldg(&w4[(kc * 16 + nt) * 32 + lane]);
            uint32_t bh0 = __float_as_uint(bq.x), bh1 = __float_as_uint(bq.y);
            uint32_t bl0 = __float_as_uint(bq.z), bl1 = __float_as_uint(bq.w);
            mma8(acc[nt], ah, bh0, bh1);
            mma8(acc[nt], al, bh0, bh1);
            mma8(acc[nt], ah, bl0, bl1);
        }
    }
}

// ---- zero deg/pool ----
__global__ void zero_misc_kernel() {
    int i = blockIdx.x * blockDim.x + threadIdx.x;
    int stride = gridDim.x * blockDim.x;
    for (int k = i; k < NN; k += stride) g_deg[k] = 0.f;
    if (blockIdx.x == 0) {
        for (int k = threadIdx.x; k < BBATCH * HH; k += blockDim.x) g_pooled[k] = 0.f;
        if (threadIdx.x < BBATCH) g_counts[threadIdx.x] = 0.f;
    }
}

// ---- convert with inline dtype detection + deg count ----
__global__ void convert_kernel(const unsigned int* __restrict__ eiu,
                               const void* __restrict__ bt) {
    int is64 = 1;
#pragma unroll
    for (int s = 0; s < 16; s++)
        if (eiu[2 * s + 1] != 0u) { is64 = 0; break; }
    const void* ei = (const void*)eiu;
    int i = blockIdx.x * blockDim.x + threadIdx.x;
    int stride = gridDim.x * blockDim.x;
    for (int k = i; k < EE; k += stride) {
        int s, d;
        if (is64) {
            s = (int)((const long long*)ei)[k];
            d = (int)((const long long*)ei)[EE + k];
        } else {
            s = ((const int*)ei)[k];
            d = ((const int*)ei)[EE + k];
        }
        g_src[k] = s;
        g_dst[k] = d;
        atomicAdd(&g_deg[d], 1.f);
    }
    for (int k = i; k < NN; k += stride)
        g_batchv[k] = is64 ? (int)((const long long*)bt)[k] : ((const int*)bt)[k];
}

__global__ void node_embed_kernel(const float* __restrict__ x,
                                  const float* __restrict__ Wn,
                                  const float* __restrict__ bn) {
    __shared__ float sW[NDIM * HH];
    __shared__ float sb[HH];
    for (int i = threadIdx.x; i < NDIM * HH; i += blockDim.x) sW[i] = Wn[i];
    if (threadIdx.x < HH) sb[threadIdx.x] = bn[threadIdx.x];
    __syncthreads();
    int g = blockIdx.x * blockDim.x + threadIdx.x;
    int stride = gridDim.x * blockDim.x;
    const int total = NN * 32;
    for (; g < total; g += stride) {
        int n = g >> 5;
        int c = (g & 31) * 4;
        const float* xr = x + (size_t)n * NDIM;
        float4 o = make_float4(sb[c], sb[c + 1], sb[c + 2], sb[c + 3]);
#pragma unroll
        for (int k = 0; k < NDIM; k++) {
            float a = __ldg(xr + k);
            float4 w = *(const float4*)&sW[k * HH + c];
            o.x = fmaf(a, w.x, o.x); o.y = fmaf(a, w.y, o.y);
            o.z = fmaf(a, w.z, o.z); o.w = fmaf(a, w.w, o.w);
        }
        *(float4*)&g_h[(size_t)n * HH + c] = o;
    }
}

// ---- unified weight prep: grid (LL, 97), block 512 ----
// y<17: Wec/b1e (+bf at y==16)
// [17,33): uW2 frags   [33,49): Wf frags (computed inline)
// [49,65): W1a frags   [65,81): W1b frags   [81,97): uW1a frags
__global__ void prep_kernel(const float* __restrict__ We, const float* __restrict__ be,
                            const float* __restrict__ mW1, const float* __restrict__ mb1,
                            const float* __restrict__ mW2, const float* __restrict__ mb2,
                            const float* __restrict__ uW1, const float* __restrict__ uW2) {
    const int l = blockIdx.x, y = blockIdx.y;
    const int t = threadIdx.x;
    if (y < 17) {
        __shared__ float srow[HH];
        const float* W1c = mW1 + (size_t)l * 3 * HH * HH + 2 * HH * HH;
        if (t < HH) srow[t] = (y < EDIM) ? We[y * HH + t] : be[t];
        __syncthreads();
        if (t < HH) {
            float s = (y < EDIM) ? 0.f : mb1[l * HH + t];
            for (int j = 0; j < HH; j++)
                s = fmaf(srow[j], W1c[j * HH + t], s);
            if (y < EDIM) g_wec[(size_t)l * EDIM * HH + y * HH + t] = s;
            else          g_b1e[l * HH + t] = s;
        } else if (y == 16 && t < 256) {
            const int c = t - HH;
            const float* u1b = uW1 + (size_t)l * 2 * HH * HH + HH * HH;
            float s = 0.f;
            for (int n = 0; n < HH; n++)
                s = fmaf(mb2[l * HH + n], u1b[n * HH + c], s);
            g_bf[l * HH + c] = s;
        }
        return;
    }
    const int nt = t >> 5, lane = t & 31;
    const int col = nt * 8 + (lane >> 2);
    float b0, b1;
    float* outp;
    int kc;
    if (y < 33) {
        kc = y - 17;
        const float* W = uW2 + (size_t)l * HH * HH;
        int kr0 = kc * 8 + (lane & 3);
        b0 = W[kr0 * HH + col];
        b1 = W[(kr0 + 4) * HH + col];
        outp = g_uw2frag;
    } else if (y < 49) {
        kc = y - 33;
        // Wf[j][c] = sum_n mW2[j][n] * uW1b[n][c], computed inline
        const float* W2 = mW2 + (size_t)l * HH * HH;
        const float* u1b = uW1 + (size_t)l * 2 * HH * HH + HH * HH;
        int j0 = kc * 8 + (lane & 3);
        float s0 = 0.f, s1 = 0.f;
        for (int n = 0; n < HH; n++) {
            float u = __ldg(&u1b[n * HH + col]);
            s0 = fmaf(__ldg(&W2[j0 * HH + n]), u, s0);
            s1 = fmaf(__ldg(&W2[(j0 + 4) * HH + n]), u, s1);
        }
        b0 = s0; b1 = s1;
        outp = g_wffrag;
    } else {
        const float* W;
        if (y < 65)      { kc = y - 49; W = mW1 + (size_t)l * 3 * HH * HH;          outp = g_w1afrag; }
        else if (y < 81) { kc = y - 65; W = mW1 + (size_t)l * 3 * HH * HH + HH * HH; outp = g_w1bfrag; }
        else             { kc = y - 81; W = uW1 + (size_t)l * 2 * HH * HH;          outp = g_uw1afrag; }
        int kr0 = kc * 8 + (lane & 3);
        b0 = W[kr0 * HH + col];
        b1 = W[(kr0 + 4) * HH + col];
    }
    float b0h = tf32r(b0), b1h = tf32r(b1);
    float4 v = make_float4(b0h, b1h, tf32r(b0 - b0h), tf32r(b1 - b1h));
    ((float4*)outp)[((size_t)l * 256 + kc * 16 + nt) * 32 + lane] = v;
}

// ---- pa_pb via HMMA: loads h once, two B passes ----
#define SH_BYTES (128 * EMW * 4)

__global__ __launch_bounds__(256, 2)
void pa_pb2_kernel(int l) {
    extern __shared__ float sH[];
    const int tid = threadIdx.x;
    const int nbase = blockIdx.x * BM;
    {
        const int r = tid >> 1;
        const int cb = (tid & 1) * 64;
        int gnode = nbase + r;
        if (gnode >= NN) gnode = NN - 1;
        const float* hp = g_h + (size_t)gnode * HH + cb;
#pragma unroll
        for (int c = 0; c < 64; c += 4)
            *(float4*)&sH[r * EMW + cb + c] = *(const float4*)(hp + c);
    }
    __syncthreads();

    const int lane = tid & 31;
    const int wid = tid >> 5;
    const int r0 = wid * 16 + (lane >> 2);
    const int n0 = nbase + r0, n1 = nbase + r0 + 8;

#pragma unroll 1
    for (int pass = 0; pass < 2; pass++) {
        float acc[16][4];
#pragma unroll
        for (int nt = 0; nt < 16; nt++)
#pragma unroll
            for (int q = 0; q < 4; q++) acc[nt][q] = 0.f;
        const float4* w4 = (const float4*)((pass ? g_w1bfrag : g_w1afrag) + (size_t)l * 32768);
        hmma_sweep(sH, w4, r0, lane, acc);
        float* outp = pass ? g_pb : g_pa;
#pragma unroll
        for (int nt = 0; nt < 16; nt++) {
            int c = nt * 8 + 2 * (lane & 3);
            if (n0 < NN) *(float2*)&outp[(size_t)n0 * HH + c] = make_float2(acc[nt][0], acc[nt][1]);
            if (n1 < NN) *(float2*)&outp[(size_t)n1 * HH + c] = make_float2(acc[nt][2], acc[nt][3]);
        }
    }
}

__global__ void zero_S_kernel() {
    int i = blockIdx.x * blockDim.x + threadIdx.x;
    int stride = gridDim.x * blockDim.x;
    float4 z = make_float4(0.f, 0.f, 0.f, 0.f);
    const int n4 = NN * HH / 4;
    for (int k = i; k < n4; k += stride) ((float4*)g_S)[k] = z;
}

// ---- edge kernel: phase-1 only, register hidden, direct scatter ----
__global__ __launch_bounds__(256)
void edge_mlp6_kernel(const float* __restrict__ ea, int l) {
    __shared__ float sEA[2048];
    __shared__ float sWec[2048];
    __shared__ float sB1e[HH];
    __shared__ int sDst[BM];
    __shared__ int sSrc[BM];

    const int tid = threadIdx.x;
    const int ebase = blockIdx.x * BM;

    if (tid < BM) sDst[tid] = g_dst[ebase + tid];
    else          sSrc[tid - BM] = g_src[ebase + tid - BM];
    {
        const float4* s4 = (const float4*)(ea + (size_t)ebase * EDIM);
        ((float4*)sEA)[tid] = s4[tid];
        ((float4*)sEA)[tid + 256] = s4[tid + 256];
        const float4* w4 = (const float4*)(g_wec + (size_t)l * EDIM * HH);
        ((float4*)sWec)[tid] = w4[tid];
        ((float4*)sWec)[tid + 256] = w4[tid + 256];
    }
    if (tid < HH) sB1e[tid] = g_b1e[l * HH + tid];
    __syncthreads();

    const int r = tid >> 1;
    const int cb = (tid & 1) * 64;
    const int dst = sDst[r];
    const float* pa = g_pa + (size_t)dst * HH + cb;
    const float* pb = g_pb + (size_t)sSrc[r] * HH + cb;

    float4 s[16];
#pragma unroll
    for (int i = 0; i < 16; i++) {
        float4 a = *(const float4*)(pa + 4 * i);
        float4 b = *(const float4*)(pb + 4 * i);
        float4 bb = *(const float4*)(sB1e + cb + 4 * i);
        s[i].x = a.x + b.x + bb.x;
        s[i].y = a.y + b.y + bb.y;
        s[i].z = a.z + b.z + bb.z;
        s[i].w = a.w + b.w + bb.w;
    }
    float eav[16];
#pragma unroll
    for (int k = 0; k < 16; k++) eav[k] = sEA[r * EDIM + k];
#pragma unroll
    for (int k = 0; k < 16; k++) {
        float e = eav[k];
#pragma unroll
        for (int i = 0; i < 16; i++) {
            float4 w = *(const float4*)&sWec[k * HH + cb + 4 * i];
            s[i].x = fmaf(e, w.x, s[i].x);
            s[i].y = fmaf(e, w.y, s[i].y);
            s[i].z = fmaf(e, w.z, s[i].z);
            s[i].w = fmaf(e, w.w, s[i].w);
        }
    }
    float* op = g_S + (size_t)dst * HH + cb;
#pragma unroll
    for (int i = 0; i < 16; i++) {
        float vx = fmaxf(s[i].x, 0.f), vy = fmaxf(s[i].y, 0.f);
        float vz = fmaxf(s[i].z, 0.f), vw = fmaxf(s[i].w, 0.f);
        asm volatile("red.global.add.v4.f32 [%0], {%1, %2, %3, %4};"
                     :: "l"(op + 4 * i), "f"(vx), "f"(vy), "f"(vz), "f"(vw)
                     : "memory");
    }
}

// ---- node update v4: fully HMMA ----
// hidden = relu(h@uW1a + S@Wf + deg*bf + ub1); h += hidden@uW2 + ub2
__global__ __launch_bounds__(256, 2)
void node_mlp4_kernel(const float* __restrict__ b1v, int l,
                      const float* __restrict__ b2v) {
    extern __shared__ float sH[];
    const int tid = threadIdx.x;
    const int nbase = blockIdx.x * BM;
    const int lane = tid & 31;
    const int wid = tid >> 5;
    const int r0 = wid * 16 + (lane >> 2);
    const int lr = tid >> 1;
    const int cb = (tid & 1) * 64;
    int gnode = nbase + lr;
    if (gnode >= NN) gnode = NN - 1;

    // load h rows
    {
        const float* hp = g_h + (size_t)gnode * HH + cb;
#pragma unroll
        for (int c = 0; c < 64; c += 4)
            *(float4*)&sH[lr * EMW + cb + c] = *(const float4*)(hp + c);
    }
    __syncthreads();

    float acc[16][4];
#pragma unroll
    for (int nt = 0; nt < 16; nt++)
#pragma unroll
        for (int q = 0; q < 4; q++) acc[nt][q] = 0.f;

    hmma_sweep(sH, (const float4*)(g_uw1afrag + (size_t)l * 32768), r0, lane, acc);
    __syncthreads();

    // load S rows
    {
        const float* sp = g_S + (size_t)gnode * HH + cb;
#pragma unroll
        for (int c = 0; c < 64; c += 4)
            *(float4*)&sH[lr * EMW + cb + c] = *(const float4*)(sp + c);
    }
    __syncthreads();

    hmma_sweep(sH, (const float4*)(g_wffrag + (size_t)l * 32768), r0, lane, acc);
    __syncthreads();

    // bias + relu in MMA layout -> sH (hidden)
    {
        const float* bf = g_bf + l * HH;
        int m0 = nbase + r0; if (m0 >= NN) m0 = NN - 1;
        int m1 = nbase + r0 + 8; if (m1 >= NN) m1 = NN - 1;
        float dg0 = g_deg[m0], dg1 = g_deg[m1];
#pragma unroll
        for (int nt = 0; nt < 16; nt++) {
            int c = nt * 8 + 2 * (lane & 3);
            float ba = __ldg(b1v + c), bb = __ldg(b1v + c + 1);
            float fa = __ldg(bf + c), fb = __ldg(bf + c + 1);
            float h00 = fmaxf(acc[nt][0] + ba + dg0 * fa, 0.f);
            float h01 = fmaxf(acc[nt][1] + bb + dg0 * fb, 0.f);
            float h10 = fmaxf(acc[nt][2] + ba + dg1 * fa, 0.f);
            float h11 = fmaxf(acc[nt][3] + bb + dg1 * fb, 0.f);
            *(float2*)&sH[r0 * EMW + c] = make_float2(h00, h01);
            *(float2*)&sH[(r0 + 8) * EMW + c] = make_float2(h10, h11);
            acc[nt][0] = 0.f; acc[nt][1] = 0.f; acc[nt][2] = 0.f; acc[nt][3] = 0.f;
        }
    }
    __syncthreads();

    // phase 3: D = hidden @ uW2
    hmma_sweep(sH, (const float4*)(g_uw2frag + (size_t)l * 32768), r0, lane, acc);
    __syncthreads();

#pragma unroll
    for (int nt = 0; nt < 16; nt++) {
        int c = nt * 8 + 2 * (lane & 3);
        *(float2*)&sH[r0 * EMW + c] = make_float2(acc[nt][0], acc[nt][1]);
        *(float2*)&sH[(r0 + 8) * EMW + c] = make_float2(acc[nt][2], acc[nt][3]);
    }
    __syncthreads();

    // residual: h += D + b2
    {
        int node = nbase + lr;
        if (node < NN) {
            float* op = g_h + (size_t)node * HH + cb;
            const float* hrow = sH + lr * EMW + cb;
#pragma unroll
            for (int c = 0; c < 64; c += 4) {
                float4 v = *(const float4*)(hrow + c);
                float4 b = __ldg((const float4*)(b2v + cb + c));
                float4 o = *(float4*)(op + c);
                o.x += v.x + b.x; o.y += v.y + b.y;
                o.z += v.z + b.z; o.w += v.w + b.w;
                *(float4*)(op + c) = o;
            }
        }
    }
}

__global__ void pool_kernel() {
    __shared__ float sp[BBATCH * HH];
    __shared__ float sc[BBATCH];
    for (int i = threadIdx.x; i < BBATCH * HH; i += blockDim.x) sp[i] = 0.f;
    if (threadIdx.x < BBATCH) sc[threadIdx.x] = 0.f;
    __syncthreads();
    int g = blockIdx.x * blockDim.x + threadIdx.x;
    int stride = gridDim.x * blockDim.x;
    const int total = NN * HH;
    for (int idx = g; idx < total; idx += stride) {
        int n = idx >> 7;
        int j = idx & 127;
        int b = g_batchv[n];
        atomicAdd(&sp[b * HH + j], g_h[idx]);
        if (j == 0) atomicAdd(&sc[b], 1.f);
    }
    __syncthreads();
    for (int i = threadIdx.x; i < BBATCH * HH; i += blockDim.x)
        atomicAdd(&g_pooled[i], sp[i]);
    if (threadIdx.x < BBATCH) atomicAdd(&g_counts[threadIdx.x], sc[threadIdx.x]);
}

__global__ void readout_kernel(const float* __restrict__ gf,
                               const float* __restrict__ Wg, const float* __restrict__ bg,
                               const float* __restrict__ rW1, const float* __restrict__ rb1,
                               const float* __restrict__ rW2, const float* __restrict__ rb2,
                               const float* __restrict__ rW3, const float* __restrict__ rb3,
                               float* __restrict__ out) {
    __shared__ float fin[BBATCH * 2 * HH];
    __shared__ float h1[BBATCH * HH];
    __shared__ float h2[BBATCH * 64];
    const int t = threadIdx.x;
    for (int idx = t; idx < BBATCH * 2 * HH; idx += blockDim.x) {
        int b = idx >> 8;
        int c = idx & 255;
        float v;
        if (c < HH) {
            float cnt = g_counts[b];
            if (cnt < 1.f) cnt = 1.f;
            v = g_pooled[b * HH + c] / cnt;
        } else {
            v = gf[b] * Wg[c - HH] + bg[c - HH];
        }
        fin[idx] = v;
    }
    __syncthreads();
    for (int idx = t; idx < BBATCH * HH; idx += blockDim.x) {
        int b = idx >> 7;
        int j = idx & 127;
        float s = rb1[j];
        for (int k = 0; k < 2 * HH; k++)
            s = fmaf(fin[b * 256 + k], rW1[k * HH + j], s);
        h1[idx] = (s > 0.f) ? s : 0.f;
    }
    __syncthreads();
    for (int idx = t; idx < BBATCH * 64; idx += blockDim.x) {
        int b = idx >> 6;
        int j = idx & 63;
        float s = rb2[j];
        for (int k = 0; k < HH; k++)
            s = fmaf(h1[b * HH + k], rW2[k * 64 + j], s);
        h2[idx] = (s > 0.f) ? s : 0.f;
    }
    __syncthreads();
    if (t < BBATCH) {
        float s = rb3[0];
        for (int k = 0; k < 64; k++)
            s = fmaf(h2[t * 64 + k], rW3[k], s);
        out[t] = s;
    }
}

// ---- host launcher ----
extern "C" void kernel_launch(void* const* d_in, const int* in_sizes, int n_in,
                              void* d_out, int out_size) {
    const float *x = 0, *ea = 0, *gf = 0;
    const void  *ei = 0, *bt = 0;
    const float *Wn = 0, *bn = 0, *We = 0, *be = 0, *Wg = 0, *bg = 0;
    const float *mW1 = 0, *mb1 = 0, *mW2 = 0, *mb2 = 0;
    const float *uW1 = 0, *ub1 = 0, *uW2 = 0, *ub2 = 0;
    const float *rW1 = 0, *rb1 = 0, *rW2 = 0, *rb2 = 0, *rW3 = 0, *rb3 = 0;
    int c128 = 0, c384 = 0, c49 = 0, c64 = 0;
    for (int i = 0; i < n_in; i++) {
        const void* p = d_in[i];
        switch (in_sizes[i]) {
            case 1600000: x = (const float*)p; break;
            case 6400000: ea = (const float*)p; break;
            case 8:       gf = (const float*)p; break;
            case 800000:  ei = p; break;
            case 50000:   bt = p; break;
            case 4096:    Wn = (const float*)p; break;
            case 2048:    We = (const float*)p; break;
            case 147456:  mW1 = (const float*)p; break;
            case 98304:   uW1 = (const float*)p; break;
            case 32768:   rW1 = (const float*)p; break;
            case 8192:    rW2 = (const float*)p; break;
            case 1:       rb3 = (const float*)p; break;
            case 128:
                if (c128 == 0) bn = (const float*)p;
                else if (c128 == 1) be = (const float*)p;
                else if (c128 == 2) Wg = (const float*)p;
                else if (c128 == 3) bg = (const float*)p;
                else rb1 = (const float*)p;
                c128++;
                break;
            case 384:
                if (c384 == 0) mb1 = (const float*)p;
                else if (c384 == 1) mb2 = (const float*)p;
                else if (c384 == 2) ub1 = (const float*)p;
                else ub2 = (const float*)p;
                c384++;
                break;
            case 49152:
                if (c49 == 0) mW2 = (const float*)p;
                else uW2 = (const float*)p;
                c49++;
                break;
            case 64:
                if (c64 == 0) rb2 = (const float*)p;
                else rW3 = (const float*)p;
                c64++;
                break;
            default: break;
        }
    }
    float* out = (float*)d_out;
    (void)out_size;

    cudaFuncSetAttribute(pa_pb2_kernel, cudaFuncAttributeMaxDynamicSharedMemorySize, SH_BYTES);
    cudaFuncSetAttribute(node_mlp4_kernel, cudaFuncAttributeMaxDynamicSharedMemorySize, SH_BYTES);

    const int NB_NODE = (NN + BM - 1) / BM;

    zero_misc_kernel<<<256, 256>>>();
    convert_kernel<<<1024, 256>>>((const unsigned int*)ei, bt);
    node_embed_kernel<<<3200, 256>>>(x, Wn, bn);
    prep_kernel<<<dim3(LL, 97), 512>>>(We, be, mW1, mb1, mW2, mb2, uW1, uW2);

    for (int l = 0; l < LL; l++) {
        zero_S_kernel<<<1600, 256>>>();
        pa_pb2_kernel<<<NB_NODE, 256, SH_BYTES>>>(l);
        edge_mlp6_kernel<<<EE / BM, 256>>>(ea, l);
        node_mlp4_kernel<<<NB_NODE, 256, SH_BYTES>>>(ub1 + l * HH, l, ub2 + l * HH);
    }

    pool_kernel<<<1024, 256>>>();
    readout_kernel<<<1, 256>>>(gf, Wg, bg, rW1, rb1, rW2, rb2, rW3, rb3, out);
}